// round 3
// baseline (speedup 1.0000x reference)
#include <cuda_runtime.h>
#include <math.h>

// ---------------------------------------------------------------------------
// PrettyPCF fused single-kernel: Na=Nb=1536, 50 bins.
// R3: everything in ONE kernel, 128 blocks (single wave on 148 SMs).
//  * per-block: compute perimeter weights for its 12 i-points (600 items),
//    stage B tile in shared, survivor-queue pair phase (lane==bin),
//    block partials -> global atomic; last block finalizes + resets state.
//  * queue entry packed into one u32: float u with ii in mantissa low 4 bits.
// ---------------------------------------------------------------------------

#define NPTS   1536
#define NBINS  50
#define TILE_I 12               // i-points per block; 1536/12 = 128 blocks
#define NBLK   (NPTS / TILE_I)  // 128
#define NTHR   256
#define NWARP  (NTHR / 32)
#define NCHUNK (NPTS / NTHR)    // 6
#define QCAP   (NTHR * TILE_I)  // 3072 worst-case survivors per chunk
#define ZC     1.2f

#define RMAX_D (2.0 * sqrt(1.0 / (2.0 * sqrt(3.0) * 1536.0)))

__device__ float g_acc[NBINS];   // zero-init at load; reset by last block
__device__ int   g_done;         // ditto

__global__ __launch_bounds__(NTHR)
void pcf_kernel(const float* __restrict__ A, const float* __restrict__ B,
                const int* __restrict__ scp, float* __restrict__ out)
{
    __shared__ float sbx[NPTS];
    __shared__ float sby[NPTS];
    __shared__ float sax[TILE_I], say[TILE_I];
    __shared__ float sw[TILE_I * NBINS];
    __shared__ unsigned qpk[QCAP];
    __shared__ float sacc[NBINS];
    __shared__ int   qcount;
    __shared__ int   is_last;

    const int tid  = threadIdx.x;
    const int lane = tid & 31;
    const int wid  = tid >> 5;
    const int i0   = blockIdx.x * TILE_I;

    // ---- Stage inputs ----
    if (tid < TILE_I) {
        sax[tid] = A[3 * (i0 + tid)];
        say[tid] = A[3 * (i0 + tid) + 1];
    }
    for (int j = tid; j < NPTS; j += NTHR) {
        sbx[j] = B[3 * j];
        sby[j] = B[3 * j + 1];
    }
    if (tid < NBINS) sacc[tid] = 0.0f;
    __syncthreads();

    // ---- Fused perimeter weights: 600 (ii, b) items over 256 threads ----
    const float TWO_PI = 6.2831853071795864769f;
    for (int t = tid; t < TILE_I * NBINS; t += NTHR) {
        int ii = t / NBINS;
        int b  = t - ii * NBINS;
        float x = sax[ii], y = say[ii];
        float rs = (float)((b + 1) * (5.0 / 50.0) * RMAX_D);
        float full = TWO_PI;
        float ex[4] = { x, 1.0f - x, y, 1.0f - y };
        float ey[4] = { y, y,        x, x        };
#pragma unroll
        for (int e = 0; e < 4; e++) {
            if (rs > ex[e]) {
                float ratio = fminf(ex[e] / rs, 1.0f);
                float alpha = acosf(ratio);
                float a1 = atan2f(ey[e],        ex[e]);
                float a2 = atan2f(1.0f - ey[e], ex[e]);
                full -= fminf(alpha, a1) + fminf(alpha, a2);
            }
        }
        float per = fminf(fmaxf(full * (1.0f / TWO_PI), 0.0f), 1.0f);
        float wv  = 1.0f / fmaxf(per, 1e-9f);
        sw[t] = fminf(wv, 4.0f);      // w >= 1, only upper clip binds
    }

    float ax[TILE_I], ay[TILE_I];
#pragma unroll
    for (int ii = 0; ii < TILE_I; ii++) {
        ax[ii] = sax[ii];
        ay[ii] = say[ii];
    }

    const int   same = *scp;
    const float invR = (float)(1.0 / RMAX_D);
    const float dmax = (float)((5.0 + (double)ZC) * RMAX_D);
    const float cut2 = dmax * dmax;

    // Per-lane register accumulators: lane l owns bins l and l+32.
    float acc1 = 0.0f, acc2 = 0.0f;
    const float z1base = 0.1f * (float)(lane + 1);   // RS[l]/RMAX

    __syncthreads();   // sw ready before phase B reads it

    for (int chunk = 0; chunk < NCHUNK; chunk++) {
        if (tid == 0) qcount = 0;
        __syncthreads();

        // ---- Phase A: distance test, push survivors (packed) ----
        int   j  = chunk * NTHR + tid;
        float bx = sbx[j], by = sby[j];
#pragma unroll
        for (int ii = 0; ii < TILE_I; ii++) {
            float dx = ax[ii] - bx;
            float dy = ay[ii] - by;
            float d2 = fmaf(dx, dx, dy * dy);
            if (d2 < cut2 && !(same && (i0 + ii) == j)) {
                int slot = atomicAdd(&qcount, 1);
                float u = sqrtf(d2) * invR;          // d / RMAX in [0, 6.2]
                qpk[slot] = (__float_as_uint(u) & ~0xFu) | (unsigned)ii;
            }
        }
        __syncthreads();

        // ---- Phase B: warps drain queue, lane == bin ----
        int nq = qcount;
        for (int e = wid; e < nq; e += NWARP) {
            unsigned pk = qpk[e];                    // LDS broadcast
            int   ii = (int)(pk & 0xFu);
            float u  = __uint_as_float(pk & ~0xFu);
            const float* wrow = &sw[ii * NBINS];
            float z1 = z1base - u;
            acc1 += __expf(-16.0f * z1 * z1) * wrow[lane];
            if (lane < NBINS - 32) {
                float z2 = z1 + 3.2f;
                acc2 += __expf(-16.0f * z2 * z2) * wrow[lane + 32];
            }
        }
        __syncthreads();   // protect qcount/qpk reuse next chunk
    }

    // ---- Block reduction -> global ----
    atomicAdd(&sacc[lane], acc1);
    if (lane < NBINS - 32) atomicAdd(&sacc[lane + 32], acc2);
    __syncthreads();
    if (tid < NBINS) atomicAdd(&g_acc[tid], sacc[tid]);

    // ---- Last block finalizes ----
    __threadfence();
    if (tid == 0) {
        int v = atomicAdd(&g_done, 1);
        is_last = (v == NBLK - 1);
    }
    __syncthreads();
    if (is_last) {
        if (tid < NBINS) {
            int b = tid;
            double rs_d  = (b + 1) * (5.0 / 50.0) * RMAX_D;
            double inner = fmax(0.0, rs_d - 0.5 * RMAX_D);
            double outer = rs_d + 0.5 * RMAX_D;
            float  area  = (float)(M_PI * (outer * outer - inner * inner));
            const float GF = (float)(1.0 / (sqrt(M_PI) * 0.25));

            float s   = g_acc[b] * GF;
            float pcf = s / 1536.0f / (area * 1536.0f);

            out[2 * b]     = (float)rs_d / (float)RMAX_D;
            out[2 * b + 1] = pcf;

            g_acc[b] = 0.0f;          // reset for next graph replay
        }
        if (tid == 0) g_done = 0;
    }
}

// ---------------------------------------------------------------------------
extern "C" void kernel_launch(void* const* d_in, const int* in_sizes, int n_in,
                              void* d_out, int out_size)
{
    const float* A  = (const float*)d_in[0];   // disks_a [1536,3]
    const float* B  = (const float*)d_in[1];   // disks_b [1536,3]
    const int*   sc = (const int*)d_in[2];     // same_category scalar
    float* out = (float*)d_out;

    pcf_kernel<<<NBLK, NTHR>>>(A, B, sc, out);
}

// round 4
// speedup vs baseline: 2.0063x; 2.0063x over previous
#include <cuda_runtime.h>
#include <math.h>

// ---------------------------------------------------------------------------
// PrettyPCF fused single-kernel, R4.
// Lesson from R3: this kernel is latency-bound; it needs warps/SM, not a
// "single wave". Grid is decoupled from the i-tiling by splitting the
// j-range across blocks: 192 i-tiles x 3 j-splits = 576 blocks (~4/SM).
//  * per-block: weights for its 8 i-points (400 items, duplicated across
//    j-splits - negligible), stage 512-pt B slice, survivor queue,
//    warp-per-entry with lane==bin, 2-way ILP unroll.
//  * last block (done-counter) finalizes and resets state for graph replay.
// ---------------------------------------------------------------------------

#define NPTS   1536
#define NBINS  50
#define TILE_I 8
#define ITILES (NPTS / TILE_I)    // 192
#define JSPLIT 3
#define JLEN   (NPTS / JSPLIT)    // 512
#define NBLK   (ITILES * JSPLIT)  // 576
#define NTHR   256
#define NWARP  (NTHR / 32)
#define NCHUNK (JLEN / NTHR)      // 2
#define QCAP   (NTHR * TILE_I)    // 2048 worst-case survivors per chunk
#define ZC     1.2f

#define RMAX_D (2.0 * sqrt(1.0 / (2.0 * sqrt(3.0) * 1536.0)))

__device__ float g_acc[NBINS];   // zero-init at load; reset by last block
__device__ int   g_done;

__global__ __launch_bounds__(NTHR)
void pcf_kernel(const float* __restrict__ A, const float* __restrict__ B,
                const int* __restrict__ scp, float* __restrict__ out)
{
    __shared__ float sbx[JLEN];
    __shared__ float sby[JLEN];
    __shared__ float sax[TILE_I], say[TILE_I];
    __shared__ float sw[TILE_I * NBINS];
    __shared__ unsigned qpk[QCAP];
    __shared__ float sacc[NBINS];
    __shared__ int   qcount;
    __shared__ int   is_last;

    const int tid   = threadIdx.x;
    const int lane  = tid & 31;
    const int wid   = tid >> 5;
    const int itile = blockIdx.x / JSPLIT;
    const int jsp   = blockIdx.x - itile * JSPLIT;
    const int i0    = itile * TILE_I;
    const int j0    = jsp * JLEN;

    // ---- Stage inputs ----
    if (tid < TILE_I) {
        sax[tid] = A[3 * (i0 + tid)];
        say[tid] = A[3 * (i0 + tid) + 1];
    }
    for (int j = tid; j < JLEN; j += NTHR) {
        sbx[j] = B[3 * (j0 + j)];
        sby[j] = B[3 * (j0 + j) + 1];
    }
    if (tid < NBINS) sacc[tid] = 0.0f;
    __syncthreads();

    // ---- Perimeter weights for this tile's 8 i-points (400 items) ----
    const float TWO_PI = 6.2831853071795864769f;
    for (int t = tid; t < TILE_I * NBINS; t += NTHR) {
        int ii = t / NBINS;
        int b  = t - ii * NBINS;
        float x = sax[ii], y = say[ii];
        float rs = (float)((b + 1) * (5.0 / 50.0) * RMAX_D);
        float full = TWO_PI;
        float ex[4] = { x, 1.0f - x, y, 1.0f - y };
        float ey[4] = { y, y,        x, x        };
#pragma unroll
        for (int e = 0; e < 4; e++) {
            if (rs > ex[e]) {
                float ratio = fminf(ex[e] / rs, 1.0f);
                float alpha = acosf(ratio);
                float a1 = atan2f(ey[e],        ex[e]);
                float a2 = atan2f(1.0f - ey[e], ex[e]);
                full -= fminf(alpha, a1) + fminf(alpha, a2);
            }
        }
        float per = fminf(fmaxf(full * (1.0f / TWO_PI), 0.0f), 1.0f);
        float wv  = 1.0f / fmaxf(per, 1e-9f);
        sw[t] = fminf(wv, 4.0f);
    }

    float ax[TILE_I], ay[TILE_I];
#pragma unroll
    for (int ii = 0; ii < TILE_I; ii++) {
        ax[ii] = sax[ii];
        ay[ii] = say[ii];
    }

    const int   same = *scp;
    const float invR = (float)(1.0 / RMAX_D);
    const float dmax = (float)((5.0 + (double)ZC) * RMAX_D);
    const float cut2 = dmax * dmax;

    float acc1 = 0.0f, acc2 = 0.0f;                 // lane owns bins l, l+32
    const float z1base = 0.1f * (float)(lane + 1);  // RS[l]/RMAX

    __syncthreads();   // sw ready

    for (int chunk = 0; chunk < NCHUNK; chunk++) {
        if (tid == 0) qcount = 0;
        __syncthreads();

        // ---- Phase A: distance test, push survivors (packed u|ii) ----
        int   jl = chunk * NTHR + tid;              // local j in [0,JLEN)
        int   jg = j0 + jl;                         // global j
        float bx = sbx[jl], by = sby[jl];
#pragma unroll
        for (int ii = 0; ii < TILE_I; ii++) {
            float dx = ax[ii] - bx;
            float dy = ay[ii] - by;
            float d2 = fmaf(dx, dx, dy * dy);
            if (d2 < cut2 && !(same && (i0 + ii) == jg)) {
                int slot = atomicAdd(&qcount, 1);
                float u = sqrtf(d2) * invR;         // d/RMAX in [0, 6.2]
                qpk[slot] = (__float_as_uint(u) & ~0xFu) | (unsigned)ii;
            }
        }
        __syncthreads();

        // ---- Phase B: warps drain queue, lane == bin, 2-way unroll ----
        int nq = qcount;
        int e  = wid;
        for (; e + NWARP < nq; e += 2 * NWARP) {
            unsigned pkA = qpk[e];
            unsigned pkB = qpk[e + NWARP];
            int   iiA = (int)(pkA & 0xFu);
            int   iiB = (int)(pkB & 0xFu);
            float uA  = __uint_as_float(pkA & ~0xFu);
            float uB  = __uint_as_float(pkB & ~0xFu);
            float wA1 = sw[iiA * NBINS + lane];
            float wB1 = sw[iiB * NBINS + lane];
            float zA1 = z1base - uA;
            float zB1 = z1base - uB;
            acc1 += __expf(-16.0f * zA1 * zA1) * wA1;
            acc1 += __expf(-16.0f * zB1 * zB1) * wB1;
            if (lane < NBINS - 32) {
                float zA2 = zA1 + 3.2f;
                float zB2 = zB1 + 3.2f;
                acc2 += __expf(-16.0f * zA2 * zA2) * sw[iiA * NBINS + lane + 32];
                acc2 += __expf(-16.0f * zB2 * zB2) * sw[iiB * NBINS + lane + 32];
            }
        }
        if (e < nq) {
            unsigned pk = qpk[e];
            int   ii = (int)(pk & 0xFu);
            float u  = __uint_as_float(pk & ~0xFu);
            float z1 = z1base - u;
            acc1 += __expf(-16.0f * z1 * z1) * sw[ii * NBINS + lane];
            if (lane < NBINS - 32) {
                float z2 = z1 + 3.2f;
                acc2 += __expf(-16.0f * z2 * z2) * sw[ii * NBINS + lane + 32];
            }
        }
        __syncthreads();   // protect qcount/qpk reuse
    }

    // ---- Block reduction -> global ----
    atomicAdd(&sacc[lane], acc1);
    if (lane < NBINS - 32) atomicAdd(&sacc[lane + 32], acc2);
    __syncthreads();
    if (tid < NBINS) atomicAdd(&g_acc[tid], sacc[tid]);

    // ---- Last block finalizes ----
    __threadfence();
    if (tid == 0) {
        int v = atomicAdd(&g_done, 1);
        is_last = (v == NBLK - 1);
    }
    __syncthreads();
    if (is_last) {
        if (tid < NBINS) {
            int b = tid;
            double rs_d  = (b + 1) * (5.0 / 50.0) * RMAX_D;
            double inner = fmax(0.0, rs_d - 0.5 * RMAX_D);
            double outer = rs_d + 0.5 * RMAX_D;
            float  area  = (float)(M_PI * (outer * outer - inner * inner));
            const float GF = (float)(1.0 / (sqrt(M_PI) * 0.25));

            float s   = g_acc[b] * GF;
            float pcf = s / 1536.0f / (area * 1536.0f);

            out[2 * b]     = (float)rs_d / (float)RMAX_D;
            out[2 * b + 1] = pcf;

            g_acc[b] = 0.0f;          // reset for next graph replay
        }
        if (tid == 0) g_done = 0;
    }
}

// ---------------------------------------------------------------------------
extern "C" void kernel_launch(void* const* d_in, const int* in_sizes, int n_in,
                              void* d_out, int out_size)
{
    const float* A  = (const float*)d_in[0];   // disks_a [1536,3]
    const float* B  = (const float*)d_in[1];   // disks_b [1536,3]
    const int*   sc = (const int*)d_in[2];     // same_category scalar
    float* out = (float*)d_out;

    pcf_kernel<<<NBLK, NTHR>>>(A, B, sc, out);
}